// round 7
// baseline (speedup 1.0000x reference)
#include <cuda_runtime.h>
#include <cstdint>

// Problem constants
#define SEQ_L   2048      // SEQ_LEN - 1
#define NFEAT   11
#define NBATCH  1024
#define TPB     256
#define HALF    (SEQ_L / 2)          // 1024 elements per CTA
#define EPT     (HALF / TPB)         // 4 gathered elements per thread

// Mask rows as 8-bit masks, bit i = mask element i.
//  0:[0,1,0,0,0,0,0,0]=0x02  1:[0,1,1,0,0,0,0,0]=0x06  2:[0,0,0,0,1,0,0,0]=0x10
//  3:[0,0,0,1,1,1,1,1]=0xF8  7:[0,0,0,0,0,0,0,1]=0x80  4,5,6,8 = 0
#define B_FULL  0xF8u
#define B_NO_TS 0x20u
#define B_NO_TP 0x40u

__device__ __forceinline__ unsigned base_bits(int v) {
    unsigned b = 0u;
    b = (v == 0) ? 0x02u : b;
    b = (v == 1) ? 0x06u : b;
    b = (v == 2) ? 0x10u : b;
    b = (v == 3) ? 0xF8u : b;
    b = (v == 7) ? 0x80u : b;
    return b;
}

__device__ __forceinline__ uint32_t smem_u32(const void* p) {
    uint32_t a;
    asm("{ .reg .u64 t; cvta.to.shared.u64 t, %1; cvt.u32.u64 %0, t; }"
        : "=r"(a) : "l"(p));
    return a;
}

__device__ __forceinline__ int dsmem_ld_s32(uint32_t local_addr, uint32_t rank) {
    uint32_t remote; int v;
    asm volatile("mapa.shared::cluster.u32 %0, %1, %2;"
                 : "=r"(remote) : "r"(local_addr), "r"(rank));
    asm volatile("ld.shared::cluster.s32 %0, [%1];" : "=r"(v) : "r"(remote));
    return v;
}

__device__ __forceinline__ uint4 expand4(unsigned nib) {
    uint4 r;
    r.x = (nib & 1u) ? 0x3F800000u : 0u;
    r.y = (nib & 2u) ? 0x3F800000u : 0u;
    r.z = (nib & 4u) ? 0x3F800000u : 0u;
    r.w = (nib & 8u) ? 0x3F800000u : 0u;
    return r;
}

__global__ __launch_bounds__(TPB) __cluster_dims__(2, 1, 1)
void mask_type_prob_kernel(const int* __restrict__ in,
                           uint4* __restrict__ out) {
    const int b   = blockIdx.x >> 1;
    const int h   = blockIdx.x & 1;     // which half of the row
    const int tid = threadIdx.x;

    __shared__ uint4 sbuf[HALF * 2];    // 32 KB: final float masks for this half
    __shared__ int sF[2];               // this CTA's local (f5, f6)
    __shared__ int s5[TPB / 32];
    __shared__ int s6[TPB / 32];

    const int tbase = h * HALF;
    const int* row = in + (size_t)b * SEQ_L * NFEAT;

    // ---- Pass 1: gather this half's gt values, local first occurrence ----
    int g[EPT];
    int f5 = SEQ_L, f6 = SEQ_L;   // sentinel "never"

#pragma unroll
    for (int k = 0; k < EPT; ++k) {
        const int t = tbase + tid + k * TPB;
        const int v = __ldcs(row + (size_t)t * NFEAT);
        g[k] = v;
        if (v == 5) f5 = min(f5, t);
        if (v == 6) f6 = min(f6, t);
    }

#pragma unroll
    for (int off = 16; off > 0; off >>= 1) {
        f5 = min(f5, __shfl_down_sync(0xFFFFFFFFu, f5, off));
        f6 = min(f6, __shfl_down_sync(0xFFFFFFFFu, f6, off));
    }
    const int lane = tid & 31;
    const int wid  = tid >> 5;
    if (lane == 0) { s5[wid] = f5; s6[wid] = f6; }
    __syncthreads();
    if (tid == 0) {
        int F5l = SEQ_L, F6l = SEQ_L;
#pragma unroll
        for (int i = 0; i < TPB / 32; ++i) {
            F5l = min(F5l, s5[i]);
            F6l = min(F6l, s6[i]);
        }
        sF[0] = F5l;
        sF[1] = F6l;
    }

    // ---- Cluster exchange: combine halves' minima ----
    asm volatile("barrier.cluster.arrive.aligned;" ::: "memory");
    asm volatile("barrier.cluster.wait.aligned;" ::: "memory");

    const uint32_t peer = (uint32_t)(h ^ 1);
    const uint32_t sF_addr = smem_u32(sF);
    const int F5 = min(sF[0], dsmem_ld_s32(sF_addr,     peer));
    const int F6 = min(sF[1], dsmem_ld_s32(sF_addr + 4, peer));

    asm volatile("barrier.cluster.arrive.aligned;" ::: "memory");
    asm volatile("barrier.cluster.wait.aligned;" ::: "memory");

    // ---- Pass 1.5: resolve masks, expand to floats directly in smem ----
#pragma unroll
    for (int k = 0; k < EPT; ++k) {
        const int tl = tid + k * TPB;      // local element index
        const int t  = tbase + tl;
        const int v  = g[k];
        unsigned bits;
        if (v >= 4 && v <= 6) {
            // cumsum==0 over prefix [0, pe]  <=>  first occurrence > pe
            const int pe = min(t + 1, SEQ_L - 1);
            bits = (F5 > pe) ? B_NO_TS : ((F6 > pe) ? B_NO_TP : B_FULL);
        } else {
            const int c = v < 0 ? 0 : (v > 8 ? 8 : v);
            bits = base_bits(c);
        }
        sbuf[tl * 2 + 0] = expand4(bits);
        sbuf[tl * 2 + 1] = expand4(bits >> 4);
    }
    __syncthreads();

    // ---- Pass 2: one TMA bulk store of the whole 32 KB half-row ----
    asm volatile("fence.proxy.async.shared::cta;" ::: "memory");
    if (tid == 0) {
        uint4* gdst = out + (size_t)b * (SEQ_L * 2) + (size_t)h * (HALF * 2);
        const uint32_t ssrc = smem_u32(sbuf);
        asm volatile(
            "cp.async.bulk.global.shared::cta.bulk_group [%0], [%1], %2;"
            :: "l"(gdst), "r"(ssrc), "n"(HALF * 2 * (int)sizeof(uint4))
            : "memory");
        asm volatile("cp.async.bulk.commit_group;" ::: "memory");
        asm volatile("cp.async.bulk.wait_group 0;" ::: "memory");
    }
}

extern "C" void kernel_launch(void* const* d_in, const int* in_sizes, int n_in,
                              void* d_out, int out_size) {
    const int* in = (const int*)d_in[0];
    uint4* out = (uint4*)d_out;   // float32 output: 8 floats per (b,t)
    mask_type_prob_kernel<<<NBATCH * 2, TPB>>>(in, out);
}

// round 8
// speedup vs baseline: 1.1482x; 1.1482x over previous
#include <cuda_runtime.h>
#include <cstdint>

// Problem constants
#define SEQ_L   2048      // SEQ_LEN - 1
#define NFEAT   11
#define NBATCH  1024
#define TPB     256
#define EPT     (SEQ_L / TPB)        // 8 gt values per thread (pass 1)
#define SPT     (SEQ_L * 2 / TPB)    // 16 uint4 output slots per thread (pass 2)

// Mask rows as 8-bit masks, bit i = mask element i.
//  0:[0,1,0,0,0,0,0,0]=0x02  1:[0,1,1,0,0,0,0,0]=0x06  2:[0,0,0,0,1,0,0,0]=0x10
//  3:[0,0,0,1,1,1,1,1]=0xF8  7:[0,0,0,0,0,0,0,1]=0x80  4,5,6,8 = 0
#define B_FULL  0xF8u
#define B_NO_TS 0x20u
#define B_NO_TP 0x40u

__device__ __forceinline__ unsigned base_bits(int v) {
    unsigned b = 0u;
    b = (v == 0) ? 0x02u : b;
    b = (v == 1) ? 0x06u : b;
    b = (v == 2) ? 0x10u : b;
    b = (v == 3) ? 0xF8u : b;
    b = (v == 7) ? 0x80u : b;
    return b;
}

__device__ __forceinline__ uint4 expand4(unsigned nib) {
    // nib: low 4 bits -> 4 floats (0.0 / 1.0)
    uint4 r;
    r.x = (nib & 1u) ? 0x3F800000u : 0u;
    r.y = (nib & 2u) ? 0x3F800000u : 0u;
    r.z = (nib & 4u) ? 0x3F800000u : 0u;
    r.w = (nib & 8u) ? 0x3F800000u : 0u;
    return r;
}

__global__ __launch_bounds__(TPB)
void mask_type_prob_kernel(const int* __restrict__ in,
                           uint4* __restrict__ out) {
    const int b   = blockIdx.x;
    const int tid = threadIdx.x;

    __shared__ unsigned char sv[SEQ_L];   // gt value per t (0..8 fits a byte)
    __shared__ int s5[TPB / 32];
    __shared__ int s6[TPB / 32];

    const int* row = in + (size_t)b * SEQ_L * NFEAT;

    // ---- Pass 1: strided gather of gt, first occurrence of 5 / 6 ----
    int f5 = SEQ_L;   // sentinel: "never", > any prefix end
    int f6 = SEQ_L;

#pragma unroll
    for (int k = 0; k < EPT; ++k) {
        const int t = tid + k * TPB;
        const int v = __ldg(row + (size_t)t * NFEAT);   // default/ca: keep in L2
        sv[t] = (unsigned char)v;
        if (v == 5) f5 = min(f5, t);
        if (v == 6) f6 = min(f6, t);
    }

#pragma unroll
    for (int off = 16; off > 0; off >>= 1) {
        f5 = min(f5, __shfl_down_sync(0xFFFFFFFFu, f5, off));
        f6 = min(f6, __shfl_down_sync(0xFFFFFFFFu, f6, off));
    }
    const int lane = tid & 31;
    const int wid  = tid >> 5;
    if (lane == 0) { s5[wid] = f5; s6[wid] = f6; }
    __syncthreads();   // covers sv[] and s5/s6

    int F5 = SEQ_L, F6 = SEQ_L;
#pragma unroll
    for (int i = 0; i < TPB / 32; ++i) {
        F5 = min(F5, s5[i]);
        F6 = min(F6, s6[i]);
    }

    // ---- Pass 2: slot-mapped, fully coalesced evict-first stores ----
    // output row = 2048 elements * 2 uint4 = 4096 uint4 slots.
    // slot s -> element t = s>>1, half = s&1. Warp writes 512 contiguous bytes.
    uint4* orow = out + (size_t)b * (SEQ_L * 2);

#pragma unroll
    for (int k = 0; k < SPT; ++k) {
        const int slot = tid + k * TPB;
        const int t    = slot >> 1;
        const int half = slot & 1;

        const int v = (int)sv[t];
        unsigned bits;
        if (v >= 4 && v <= 6) {
            // cumsum(t')==0  <=>  first occurrence > pe,  pe = min(t+1, L-1)
            const int pe = min(t + 1, SEQ_L - 1);
            bits = (F5 > pe) ? B_NO_TS : ((F6 > pe) ? B_NO_TP : B_FULL);
        } else {
            bits = base_bits(v);
        }
        __stcs(orow + slot, expand4(bits >> (half * 4)));   // evict-first write
    }
}

extern "C" void kernel_launch(void* const* d_in, const int* in_sizes, int n_in,
                              void* d_out, int out_size) {
    const int* in = (const int*)d_in[0];
    uint4* out = (uint4*)d_out;   // float32 output: 8 floats per (b,t)
    mask_type_prob_kernel<<<NBATCH, TPB>>>(in, out);
}